// round 1
// baseline (speedup 1.0000x reference)
#include <cuda_runtime.h>
#include <cuda_bf16.h>

// MeshGNN on GB300: the vertex dimension is algebraically degenerate.
// h starts uniform across the 12 vertices (broadcast of text features) and the
// adjacency is row-stochastic with identical row sums s, so A@h = s*h forever.
// The whole net is a per-batch-row MLP: 384->256, 4x(256->256, *s, relu), 256->3,
// then out[b,v,:] = template[v] + d[b].
//
// fp32 compute via packed fma.rn.f32x2 (FFMA2) for 2x FMA-pipe throughput.

#define BM        64
#define KC        32
#define TD        384
#define HID       256
#define NL        4
#define NTHREADS  256

__device__ __forceinline__ unsigned long long pack_dup(float x) {
    unsigned long long r;
    asm("mov.b64 %0, {%1, %1};" : "=l"(r) : "f"(x));
    return r;
}
__device__ __forceinline__ void ffma2(unsigned long long& acc,
                                      unsigned long long a, unsigned long long b) {
    asm("fma.rn.f32x2 %0, %1, %2, %0;" : "+l"(acc) : "l"(a), "l"(b));
}
__device__ __forceinline__ float2 unpack2(unsigned long long v) {
    float2 f;
    asm("mov.b64 {%0, %1}, %2;" : "=f"(f.x), "=f"(f.y) : "l"(v));
    return f;
}

// 8 rows x 8 cols (as 4 f32x2 col-pairs) FMA micro-tile for one k-step.
#define FMA_ROW(i, hv) do {                                              \
    unsigned long long hh = pack_dup(hv);                                \
    ffma2(acc[i][0], hh, w0.x); ffma2(acc[i][1], hh, w0.y);              \
    ffma2(acc[i][2], hh, w1.x); ffma2(acc[i][3], hh, w1.y);              \
} while (0)

#define FMA_BLOCK(ha, hb, w0, w1) do {                                   \
    FMA_ROW(0, ha.x); FMA_ROW(1, ha.y); FMA_ROW(2, ha.z); FMA_ROW(3, ha.w); \
    FMA_ROW(4, hb.x); FMA_ROW(5, hb.y); FMA_ROW(6, hb.z); FMA_ROW(7, hb.w); \
} while (0)

template<bool RELU>
__device__ __forceinline__ void epilogue(unsigned long long (&acc)[8][4],
                                         float* HsT, const float* __restrict__ bias,
                                         float scale, int r0, int c0)
{
    #pragma unroll
    for (int cp = 0; cp < 4; cp++) {
        float ve[8], vo[8];
        #pragma unroll
        for (int i = 0; i < 8; i++) {
            float2 v = unpack2(acc[i][cp]);
            ve[i] = v.x; vo[i] = v.y;
        }
        int ce = c0 + 2 * cp;
        float be  = bias[ce];
        float bod = bias[ce + 1];
        #pragma unroll
        for (int i = 0; i < 8; i++) {
            float a = fmaf(scale, ve[i], be);
            float b = fmaf(scale, vo[i], bod);
            if (RELU) { a = fmaxf(a, 0.0f); b = fmaxf(b, 0.0f); }
            ve[i] = a; vo[i] = b;
        }
        *(float4*)(HsT + ce * BM + r0)           = make_float4(ve[0], ve[1], ve[2], ve[3]);
        *(float4*)(HsT + ce * BM + r0 + 4)       = make_float4(ve[4], ve[5], ve[6], ve[7]);
        *(float4*)(HsT + (ce + 1) * BM + r0)     = make_float4(vo[0], vo[1], vo[2], vo[3]);
        *(float4*)(HsT + (ce + 1) * BM + r0 + 4) = make_float4(vo[4], vo[5], vo[6], vo[7]);
    }
}

extern "C" __global__ void __launch_bounds__(NTHREADS, 2)
meshgnn_kernel(const float* __restrict__ X,   // (32768, 384)
               const float* __restrict__ Wt,  // (384, 256)
               const float* __restrict__ bt,  // (256)
               const float* __restrict__ Wg,  // (4, 256, 256)
               const float* __restrict__ bg,  // (4, 256)
               const float* __restrict__ Wo,  // (256, 3)
               const float* __restrict__ bo,  // (3)
               const float* __restrict__ Adj, // (12, 12)
               const float* __restrict__ Tm,  // (12, 3)
               float* __restrict__ Out)       // (32768, 12, 3)
{
    extern __shared__ float smembuf[];
    float* HsT = smembuf;                 // [HID][BM]  activations, transposed (k-major)
    float* Ws  = HsT + HID * BM;          // [KC][HID]  weight chunk
    float* Xs  = Ws + KC * HID;           // [KC][BM]   input chunk (GEMM1 only)
    float* Ds  = Xs + KC * BM;            // [BM*3] displacements (+pad)
    float* Wos = Ds + 256;                // [HID*3]

    const int tid  = threadIdx.x;
    const int lane = tid & 31;
    const int wrp  = tid >> 5;
    const int r0   = wrp << 3;     // 8 rows per thread (same for all lanes of a warp)
    const int c0   = lane << 3;    // 8 cols per thread
    const int row0 = blockIdx.x * BM;

    // s = adjacency row sum (identical across rows: 6 equal entries per row)
    float s = 0.0f;
    #pragma unroll
    for (int m = 0; m < 12; m++) s += Adj[m];

    unsigned long long acc[8][4];

    // ================= GEMM1: tf = X @ Wt + bt  (K = 384) =================
    #pragma unroll
    for (int i = 0; i < 8; i++)
        #pragma unroll
        for (int j = 0; j < 4; j++) acc[i][j] = 0ULL;

    for (int kc = 0; kc < TD; kc += KC) {
        // Stage X chunk, transposed: Xs[k][r]
        #pragma unroll
        for (int it = 0; it < 2; it++) {
            int i  = tid + it * NTHREADS;        // 0..511
            int r  = i >> 3;
            int k4 = (i & 7) << 2;
            float4 v = *(const float4*)(X + (size_t)(row0 + r) * TD + kc + k4);
            Xs[(k4 + 0) * BM + r] = v.x;
            Xs[(k4 + 1) * BM + r] = v.y;
            Xs[(k4 + 2) * BM + r] = v.z;
            Xs[(k4 + 3) * BM + r] = v.w;
        }
        // Stage W chunk (rows kc..kc+31 of Wt, contiguous)
        {
            const float4* src = (const float4*)(Wt + (size_t)kc * HID);
            #pragma unroll
            for (int it = 0; it < 8; it++)
                ((float4*)Ws)[tid + it * NTHREADS] = src[tid + it * NTHREADS];
        }
        __syncthreads();
        #pragma unroll 2
        for (int k = 0; k < KC; k++) {
            float4 ha = *(const float4*)(Xs + k * BM + r0);
            float4 hb = *(const float4*)(Xs + k * BM + r0 + 4);
            ulonglong2 w0 = *(const ulonglong2*)(Ws + k * HID + c0);
            ulonglong2 w1 = *(const ulonglong2*)(Ws + k * HID + c0 + 4);
            FMA_BLOCK(ha, hb, w0, w1);
        }
        __syncthreads();
    }
    epilogue<false>(acc, HsT, bt, 1.0f, r0, c0);  // tf + bt, no relu
    __syncthreads();

    // ================= GNN layers: h = relu(s*(h @ Wl) + bl) =================
    for (int l = 0; l < NL; l++) {
        const float* W = Wg + (size_t)l * HID * HID;
        #pragma unroll
        for (int i = 0; i < 8; i++)
            #pragma unroll
            for (int j = 0; j < 4; j++) acc[i][j] = 0ULL;

        for (int kc = 0; kc < HID; kc += KC) {
            const float4* src = (const float4*)(W + (size_t)kc * HID);
            #pragma unroll
            for (int it = 0; it < 8; it++)
                ((float4*)Ws)[tid + it * NTHREADS] = src[tid + it * NTHREADS];
            __syncthreads();
            #pragma unroll 2
            for (int k = 0; k < KC; k++) {
                const float* hp = HsT + (kc + k) * BM;
                float4 ha = *(const float4*)(hp + r0);
                float4 hb = *(const float4*)(hp + r0 + 4);
                ulonglong2 w0 = *(const ulonglong2*)(Ws + k * HID + c0);
                ulonglong2 w1 = *(const ulonglong2*)(Ws + k * HID + c0 + 4);
                FMA_BLOCK(ha, hb, w0, w1);
            }
            __syncthreads();   // all HsT reads complete -> safe to overwrite in epilogue
        }
        epilogue<true>(acc, HsT, bg + l * HID, s, r0, c0);
        __syncthreads();
    }

    // ================= Output: d = h @ Wo + bo; out = template + d =================
    for (int i = tid; i < HID * 3; i += NTHREADS) Wos[i] = Wo[i];
    __syncthreads();

    if (tid < 192) {
        int j = tid / 64;     // output component 0..2
        int r = tid % 64;     // row within tile
        float d = bo[j];
        #pragma unroll 8
        for (int k = 0; k < HID; k++)
            d = fmaf(HsT[k * BM + r], Wos[k * 3 + j], d);
        Ds[r * 3 + j] = d;
    }
    __syncthreads();

    float* outp = Out + (size_t)row0 * 36;
    #pragma unroll
    for (int it = 0; it < 9; it++) {          // 64 rows * 36 = 2304 elements
        int i   = tid + it * NTHREADS;
        int r   = i / 36;
        int rem = i - r * 36;
        outp[i] = Tm[rem] + Ds[r * 3 + rem % 3];
    }
}

extern "C" void kernel_launch(void* const* d_in, const int* in_sizes, int n_in,
                              void* d_out, int out_size) {
    const float* X   = (const float*)d_in[0];
    const float* Wt  = (const float*)d_in[1];
    const float* bt  = (const float*)d_in[2];
    const float* Wg  = (const float*)d_in[3];
    const float* bg  = (const float*)d_in[4];
    const float* Wo  = (const float*)d_in[5];
    const float* bo  = (const float*)d_in[6];
    const float* Adj = (const float*)d_in[7];
    const float* Tm  = (const float*)d_in[8];
    float* Out = (float*)d_out;

    const int smem_bytes = (HID * BM + KC * HID + KC * BM + 256 + HID * 3) * (int)sizeof(float);
    cudaFuncSetAttribute(meshgnn_kernel,
                         cudaFuncAttributeMaxDynamicSharedMemorySize, smem_bytes);
    meshgnn_kernel<<<32768 / BM, NTHREADS, smem_bytes>>>(X, Wt, bt, Wg, bg, Wo, bo, Adj, Tm, Out);
}

// round 2
// speedup vs baseline: 1.0010x; 1.0010x over previous
#include <cuda_runtime.h>
#include <cuda_bf16.h>

// MeshGNN on GB300: the vertex dimension is algebraically degenerate.
// h starts uniform across the 12 vertices (broadcast of text features) and the
// adjacency is row-stochastic with identical row sums s, so A@h = s*h forever.
// The whole net is a per-batch-row MLP: 384->256, 4x(256->256, *s, relu), 256->3,
// then out[b,v,:] = template[v] + d[b].
//
// fp32 compute via packed fma.rn.f32x2 (FFMA2) for 2x FMA-pipe throughput.

#define BM        64
#define KC        32
#define TD        384
#define HID       256
#define NL        4
#define NTHREADS  256

__device__ __forceinline__ unsigned long long pack_dup(float x) {
    unsigned long long r;
    asm("mov.b64 %0, {%1, %1};" : "=l"(r) : "f"(x));
    return r;
}
__device__ __forceinline__ void ffma2(unsigned long long& acc,
                                      unsigned long long a, unsigned long long b) {
    asm("fma.rn.f32x2 %0, %1, %2, %0;" : "+l"(acc) : "l"(a), "l"(b));
}
__device__ __forceinline__ float2 unpack2(unsigned long long v) {
    float2 f;
    asm("mov.b64 {%0, %1}, %2;" : "=f"(f.x), "=f"(f.y) : "l"(v));
    return f;
}

// 8 rows x 8 cols (as 4 f32x2 col-pairs) FMA micro-tile for one k-step.
#define FMA_ROW(i, hv) do {                                              \
    unsigned long long hh = pack_dup(hv);                                \
    ffma2(acc[i][0], hh, w0.x); ffma2(acc[i][1], hh, w0.y);              \
    ffma2(acc[i][2], hh, w1.x); ffma2(acc[i][3], hh, w1.y);              \
} while (0)

#define FMA_BLOCK(ha, hb, w0, w1) do {                                   \
    FMA_ROW(0, ha.x); FMA_ROW(1, ha.y); FMA_ROW(2, ha.z); FMA_ROW(3, ha.w); \
    FMA_ROW(4, hb.x); FMA_ROW(5, hb.y); FMA_ROW(6, hb.z); FMA_ROW(7, hb.w); \
} while (0)

template<bool RELU>
__device__ __forceinline__ void epilogue(unsigned long long (&acc)[8][4],
                                         float* HsT, const float* __restrict__ bias,
                                         float scale, int r0, int c0)
{
    #pragma unroll
    for (int cp = 0; cp < 4; cp++) {
        float ve[8], vo[8];
        #pragma unroll
        for (int i = 0; i < 8; i++) {
            float2 v = unpack2(acc[i][cp]);
            ve[i] = v.x; vo[i] = v.y;
        }
        int ce = c0 + 2 * cp;
        float be  = bias[ce];
        float bod = bias[ce + 1];
        #pragma unroll
        for (int i = 0; i < 8; i++) {
            float a = fmaf(scale, ve[i], be);
            float b = fmaf(scale, vo[i], bod);
            if (RELU) { a = fmaxf(a, 0.0f); b = fmaxf(b, 0.0f); }
            ve[i] = a; vo[i] = b;
        }
        *(float4*)(HsT + ce * BM + r0)           = make_float4(ve[0], ve[1], ve[2], ve[3]);
        *(float4*)(HsT + ce * BM + r0 + 4)       = make_float4(ve[4], ve[5], ve[6], ve[7]);
        *(float4*)(HsT + (ce + 1) * BM + r0)     = make_float4(vo[0], vo[1], vo[2], vo[3]);
        *(float4*)(HsT + (ce + 1) * BM + r0 + 4) = make_float4(vo[4], vo[5], vo[6], vo[7]);
    }
}

extern "C" __global__ void __launch_bounds__(NTHREADS, 2)
meshgnn_kernel(const float* __restrict__ X,   // (32768, 384)
               const float* __restrict__ Wt,  // (384, 256)
               const float* __restrict__ bt,  // (256)
               const float* __restrict__ Wg,  // (4, 256, 256)
               const float* __restrict__ bg,  // (4, 256)
               const float* __restrict__ Wo,  // (256, 3)
               const float* __restrict__ bo,  // (3)
               const float* __restrict__ Adj, // (12, 12)
               const float* __restrict__ Tm,  // (12, 3)
               float* __restrict__ Out)       // (32768, 12, 3)
{
    extern __shared__ float smembuf[];
    float* HsT = smembuf;                 // [HID][BM]  activations, transposed (k-major)
    float* Ws  = HsT + HID * BM;          // [KC][HID]  weight chunk
    float* Xs  = Ws + KC * HID;           // [KC][BM]   input chunk (GEMM1 only)
    float* Ds  = Xs + KC * BM;            // [BM*3] displacements (+pad)
    float* Wos = Ds + 256;                // [HID*3]

    const int tid  = threadIdx.x;
    const int lane = tid & 31;
    const int wrp  = tid >> 5;
    const int r0   = wrp << 3;     // 8 rows per thread (same for all lanes of a warp)
    const int c0   = lane << 3;    // 8 cols per thread
    const int row0 = blockIdx.x * BM;

    // s = adjacency row sum (identical across rows: 6 equal entries per row)
    float s = 0.0f;
    #pragma unroll
    for (int m = 0; m < 12; m++) s += Adj[m];

    unsigned long long acc[8][4];

    // ================= GEMM1: tf = X @ Wt + bt  (K = 384) =================
    #pragma unroll
    for (int i = 0; i < 8; i++)
        #pragma unroll
        for (int j = 0; j < 4; j++) acc[i][j] = 0ULL;

    for (int kc = 0; kc < TD; kc += KC) {
        // Stage X chunk, transposed: Xs[k][r]
        #pragma unroll
        for (int it = 0; it < 2; it++) {
            int i  = tid + it * NTHREADS;        // 0..511
            int r  = i >> 3;
            int k4 = (i & 7) << 2;
            float4 v = *(const float4*)(X + (size_t)(row0 + r) * TD + kc + k4);
            Xs[(k4 + 0) * BM + r] = v.x;
            Xs[(k4 + 1) * BM + r] = v.y;
            Xs[(k4 + 2) * BM + r] = v.z;
            Xs[(k4 + 3) * BM + r] = v.w;
        }
        // Stage W chunk (rows kc..kc+31 of Wt, contiguous)
        {
            const float4* src = (const float4*)(Wt + (size_t)kc * HID);
            #pragma unroll
            for (int it = 0; it < 8; it++)
                ((float4*)Ws)[tid + it * NTHREADS] = src[tid + it * NTHREADS];
        }
        __syncthreads();
        #pragma unroll 2
        for (int k = 0; k < KC; k++) {
            float4 ha = *(const float4*)(Xs + k * BM + r0);
            float4 hb = *(const float4*)(Xs + k * BM + r0 + 4);
            ulonglong2 w0 = *(const ulonglong2*)(Ws + k * HID + c0);
            ulonglong2 w1 = *(const ulonglong2*)(Ws + k * HID + c0 + 4);
            FMA_BLOCK(ha, hb, w0, w1);
        }
        __syncthreads();
    }
    epilogue<false>(acc, HsT, bt, 1.0f, r0, c0);  // tf + bt, no relu
    __syncthreads();

    // ================= GNN layers: h = relu(s*(h @ Wl) + bl) =================
    for (int l = 0; l < NL; l++) {
        const float* W = Wg + (size_t)l * HID * HID;
        #pragma unroll
        for (int i = 0; i < 8; i++)
            #pragma unroll
            for (int j = 0; j < 4; j++) acc[i][j] = 0ULL;

        for (int kc = 0; kc < HID; kc += KC) {
            const float4* src = (const float4*)(W + (size_t)kc * HID);
            #pragma unroll
            for (int it = 0; it < 8; it++)
                ((float4*)Ws)[tid + it * NTHREADS] = src[tid + it * NTHREADS];
            __syncthreads();
            #pragma unroll 2
            for (int k = 0; k < KC; k++) {
                const float* hp = HsT + (kc + k) * BM;
                float4 ha = *(const float4*)(hp + r0);
                float4 hb = *(const float4*)(hp + r0 + 4);
                ulonglong2 w0 = *(const ulonglong2*)(Ws + k * HID + c0);
                ulonglong2 w1 = *(const ulonglong2*)(Ws + k * HID + c0 + 4);
                FMA_BLOCK(ha, hb, w0, w1);
            }
            __syncthreads();   // all HsT reads complete -> safe to overwrite in epilogue
        }
        epilogue<true>(acc, HsT, bg + l * HID, s, r0, c0);
        __syncthreads();
    }

    // ================= Output: d = h @ Wo + bo; out = template + d =================
    for (int i = tid; i < HID * 3; i += NTHREADS) Wos[i] = Wo[i];
    __syncthreads();

    if (tid < 192) {
        int j = tid / 64;     // output component 0..2
        int r = tid % 64;     // row within tile
        float d = bo[j];
        #pragma unroll 8
        for (int k = 0; k < HID; k++)
            d = fmaf(HsT[k * BM + r], Wos[k * 3 + j], d);
        Ds[r * 3 + j] = d;
    }
    __syncthreads();

    float* outp = Out + (size_t)row0 * 36;
    #pragma unroll
    for (int it = 0; it < 9; it++) {          // 64 rows * 36 = 2304 elements
        int i   = tid + it * NTHREADS;
        int r   = i / 36;
        int rem = i - r * 36;
        outp[i] = Tm[rem] + Ds[r * 3 + rem % 3];
    }
}

extern "C" void kernel_launch(void* const* d_in, const int* in_sizes, int n_in,
                              void* d_out, int out_size) {
    const float* X   = (const float*)d_in[0];
    const float* Wt  = (const float*)d_in[1];
    const float* bt  = (const float*)d_in[2];
    const float* Wg  = (const float*)d_in[3];
    const float* bg  = (const float*)d_in[4];
    const float* Wo  = (const float*)d_in[5];
    const float* bo  = (const float*)d_in[6];
    const float* Adj = (const float*)d_in[7];
    const float* Tm  = (const float*)d_in[8];
    float* Out = (float*)d_out;

    const int smem_bytes = (HID * BM + KC * HID + KC * BM + 256 + HID * 3) * (int)sizeof(float);
    cudaFuncSetAttribute(meshgnn_kernel,
                         cudaFuncAttributeMaxDynamicSharedMemorySize, smem_bytes);
    meshgnn_kernel<<<32768 / BM, NTHREADS, smem_bytes>>>(X, Wt, bt, Wg, bg, Wo, bo, Adj, Tm, Out);
}